// round 2
// baseline (speedup 1.0000x reference)
#include <cuda_runtime.h>
#include <cuda_bf16.h>

// LIF recurrent scan: B independent sequential chains (rec GEMM only mixes
// within a batch row). One CTA per batch row, membrane state held in
// registers across all T steps, recurrent GEMM done as a sparse rank-k
// update from a shared-memory spike list (spikes are ~1e-5 dense).
//
// 3-buffer spike-list rotation gives exactly ONE __syncthreads per step:
//   buffer written at step t  -> read at t+1 -> zeroed at t+2 -> reused at t+3.

#define N_NEU   1024
#define THREADS 256
#define VPT     4            // neurons per thread (N_NEU / THREADS)

__global__ __launch_bounds__(THREADS, 1)
void lif_recurrent_kernel(const float* __restrict__ x,     // [B, T, N]
                          const float* __restrict__ W,     // [N, N] (out, in)
                          const float* __restrict__ bias,  // [N]
                          float* __restrict__ out,         // [B, T, N]
                          int T)
{
    const int b   = blockIdx.x;
    const int tid = threadIdx.x;
    const int n0  = tid * VPT;

    __shared__ int   s_idx[3][N_NEU];
    __shared__ float s_val[3][N_NEU];
    __shared__ int   s_cnt[3];
    if (tid < 3) s_cnt[tid] = 0;
    __syncthreads();

    float state[VPT];
    float brec[VPT];
#pragma unroll
    for (int i = 0; i < VPT; i++) {
        state[i] = 0.0f;
        brec[i]  = bias[n0 + i];
    }

    const float4* xb = reinterpret_cast<const float4*>(
                           x + (size_t)b * T * N_NEU) + tid;
    float4* ob = reinterpret_cast<float4*>(
                           out + (size_t)b * T * N_NEU) + tid;

    const int STRIDE4 = N_NEU / 4;   // float4 row stride per timestep

    // 2-deep prefetch pipeline for the input current (pure input, no deps)
    float4 xv0 = xb[0];
    float4 xv1 = (T > 1) ? xb[STRIDE4] : make_float4(0.f, 0.f, 0.f, 0.f);

    const float ALPHA = 0.9f;
    const float OMA   = 1.0f - 0.9f;   // matches jnp's (1.0 - ALPHA) in fp32

    int wb = 0, rb = 2, zb = 1;        // write / read(prev) / zero buffers

    for (int t = 0; t < T; t++) {
        float4 xv = xv0;
        xv0 = xv1;
        if (t + 2 < T) xv1 = xb[(size_t)(t + 2) * STRIDE4];

        // Issue the (usually-zero) spike count load early to hide LDS latency.
        int c_prev = s_cnt[rb];

        float xs[VPT] = { xv.x, xv.y, xv.z, xv.w };

        // act = spike(state) from state BEFORE integration (1-step delay)
        float act[VPT];
#pragma unroll
        for (int i = 0; i < VPT; i++) {
            float s = state[i];
            float a = (s > 0.0f) ? floorf(s) : 0.0f;
            act[i] = a;
            if (a != 0.0f) {                       // rare
                int p = atomicAdd(&s_cnt[wb], 1);
                s_idx[wb][p] = n0 + i;
                s_val[wb][p] = a;
            }
        }

        // Fire-and-forget store of this step's spikes (the scan output).
        ob[(size_t)t * STRIDE4] = make_float4(act[0], act[1], act[2], act[3]);

        // rec_t = act_{t-1} @ W^T + b  — sparse rank-k from previous list.
        float rec[VPT];
        if (t == 0) {
#pragma unroll
            for (int i = 0; i < VPT; i++) rec[i] = 0.0f;   // rec0 = zeros (no bias)
        } else {
#pragma unroll
            for (int i = 0; i < VPT; i++) rec[i] = brec[i];
            for (int k = 0; k < c_prev; k++) {             // almost always 0 iters
                int   j = s_idx[rb][k];
                float v = s_val[rb][k];
#pragma unroll
                for (int i = 0; i < VPT; i++)
                    rec[i] = fmaf(v, W[(size_t)(n0 + i) * N_NEU + j], rec[i]);
            }
        }

        // Zero the buffer that will be the write target at step t+2.
        // It was read at step t-1; that read completed before last barrier.
        if (tid == 0) s_cnt[zb] = 0;

        // Membrane update: subtract, then leaky integration (matches reference).
#pragma unroll
        for (int i = 0; i < VPT; i++) {
            float total = xs[i] + rec[i];
            float s     = state[i] - act[i];       // MEM_SUBTRACT = 1.0
            state[i]    = s * ALPHA + OMA * total;
        }

        __syncthreads();   // single barrier per step: wb complete, rb release

        // rotate buffers: wb -> rb -> zb -> wb
        int nwb = zb; zb = rb; rb = wb; wb = nwb;
    }
}

extern "C" void kernel_launch(void* const* d_in, const int* in_sizes, int n_in,
                              void* d_out, int out_size)
{
    const float* x    = (const float*)d_in[0];   // input_current [B, T, N]
    const float* W    = (const float*)d_in[1];   // w_rec [N, N]
    const float* bias = (const float*)d_in[2];   // b_rec [N]
    float* out = (float*)d_out;

    const int N = in_sizes[2];                   // 1024
    const int T = 1000;
    const int B = in_sizes[0] / (T * N);         // 32

    lif_recurrent_kernel<<<B, THREADS>>>(x, W, bias, out, T);
}

// round 3
// speedup vs baseline: 2.3756x; 2.3756x over previous
#include <cuda_runtime.h>
#include <cuda_bf16.h>

// LIF recurrent scan, speculative-chunk version.
//
// 1 CTA per batch row (chains are independent across batch). State lives in
// registers for all T steps. Spikes are ~6.5e-6 dense, so the per-step
// recurrent GEMM degenerates to an (almost always empty) sparse rank-k update.
//
// Key change vs R1: per-step __syncthreads is replaced by ONE barrier pair per
// CHUNK=8 steps. Within a chunk we speculate "no spikes at steps 0..S-2"
// (spikes at step S-1 only feed the NEXT chunk and never invalidate this one).
// Any mid-chunk spike sets a shared flag -> restore register snapshot and
// replay the chunk exactly with per-step barriers (rare: ~6 replays / 125
// chunks). Replay is exact recompute, so semantics are unchanged.

#define N_NEU   1024
#define THREADS 256
#define VPT     4            // neurons per thread
#define CHUNK   8            // steps per speculation chunk (divides T=1000)

__global__ __launch_bounds__(THREADS, 1)
void lif_recurrent_kernel(const float* __restrict__ x,     // [B, T, N]
                          const float* __restrict__ W,     // [N, N] (out, in)
                          const float* __restrict__ bias,  // [N]
                          float* __restrict__ out,         // [B, T, N]
                          int T)
{
    const int b   = blockIdx.x;
    const int tid = threadIdx.x;
    const int n0  = tid * VPT;

    __shared__ int   s_idx[2][N_NEU];
    __shared__ float s_val[2][N_NEU];
    __shared__ int   s_cnt[2];
    __shared__ int   s_flag;
    if (tid < 2) s_cnt[tid] = 0;
    if (tid == 0) s_flag = 0;
    __syncthreads();

    float state[VPT], brec[VPT];
#pragma unroll
    for (int i = 0; i < VPT; i++) {
        state[i] = 0.0f;
        brec[i]  = bias[n0 + i];
    }

    const float4* xb = reinterpret_cast<const float4*>(
                           x + (size_t)b * T * N_NEU) + tid;
    float4* op = reinterpret_cast<float4*>(
                           out + (size_t)b * T * N_NEU) + tid;
    const int S4 = N_NEU / 4;

    // 2-deep input prefetch pipeline (survives across chunks & rollbacks:
    // replay reloads x directly and leaves these registers untouched).
    float4 xv0 = xb[0];
    float4 xv1 = xb[S4];

    const float ALPHA = 0.9f;
    const float OMA   = 1.0f - 0.9f;

    int pb = 0, qb = 1;     // pb: prev-step spike list, qb: this chunk's output list

    for (int tc = 0; tc < T; tc += CHUNK) {
        const int c_prev = s_cnt[pb];

        float snap[VPT];
#pragma unroll
        for (int i = 0; i < VPT; i++) snap[i] = state[i];

        // ---------- fast speculative pass: no barriers ----------
#pragma unroll
        for (int s = 0; s < CHUNK; s++) {
            const int t = tc + s;
            float4 xv = xv0; xv0 = xv1;
            const int tp = (t + 2 < T) ? (t + 2) : (T - 1);   // clamp, no branch
            xv1 = xb[(size_t)tp * S4];

            float rec[VPT];
#pragma unroll
            for (int i = 0; i < VPT; i++) rec[i] = brec[i];
            if (s == 0) {   // compile-time: only step 0 sees prev-chunk spikes
                for (int k = 0; k < c_prev; k++) {
                    const int   j = s_idx[pb][k];
                    const float v = s_val[pb][k];
#pragma unroll
                    for (int i = 0; i < VPT; i++)
                        rec[i] = fmaf(v, W[(size_t)(n0 + i) * N_NEU + j], rec[i]);
                }
            }

            float act[VPT];
#pragma unroll
            for (int i = 0; i < VPT; i++) {
                const float sv = state[i];
                act[i] = (sv > 0.0f) ? floorf(sv) : 0.0f;
            }
            const float sp = (act[0] + act[1]) + (act[2] + act[3]);

            if (s < CHUNK - 1) {
                if (sp != 0.0f) s_flag = 1;          // predicated STS, rare
            } else {
                if (sp != 0.0f) {                    // last step: feeds next chunk
#pragma unroll
                    for (int i = 0; i < VPT; i++)
                        if (act[i] != 0.0f) {
                            const int p = atomicAdd(&s_cnt[qb], 1);
                            s_idx[qb][p] = n0 + i;
                            s_val[qb][p] = act[i];
                        }
                }
            }

            op[(size_t)t * S4] = make_float4(act[0], act[1], act[2], act[3]);

            const float xs[VPT] = { xv.x, xv.y, xv.z, xv.w };
#pragma unroll
            for (int i = 0; i < VPT; i++) {
                const float tot = xs[i] + rec[i];
                const float st  = state[i] - act[i];        // MEM_SUBTRACT = 1
                state[i] = st * ALPHA + OMA * tot;
            }
        }

        __syncthreads();                    // B1: flags & pushes visible
        const int f = s_flag;
        if (tid == 0 && !f) s_cnt[pb] = 0;  // retire prev list (commit only)
        __syncthreads();                    // B2: flag consumed by all

        if (f) {
            // ---------- rollback: exact replay with per-step barriers ----------
#pragma unroll
            for (int i = 0; i < VPT; i++) state[i] = snap[i];
            if (tid == 0) { s_cnt[qb] = 0; s_flag = 0; }
            __syncthreads();

            int rb = pb, wb = qb;
            for (int s = 0; s < CHUNK; s++) {
                const int t = tc + s;
                const int c = s_cnt[rb];
                const float4 xv = xb[(size_t)t * S4];

                float rec[VPT];
#pragma unroll
                for (int i = 0; i < VPT; i++) rec[i] = brec[i];
                for (int k = 0; k < c; k++) {
                    const int   j = s_idx[rb][k];
                    const float v = s_val[rb][k];
#pragma unroll
                    for (int i = 0; i < VPT; i++)
                        rec[i] = fmaf(v, W[(size_t)(n0 + i) * N_NEU + j], rec[i]);
                }

                float act[VPT];
#pragma unroll
                for (int i = 0; i < VPT; i++) {
                    const float sv = state[i];
                    act[i] = (sv > 0.0f) ? floorf(sv) : 0.0f;
                    if (act[i] != 0.0f) {
                        const int p = atomicAdd(&s_cnt[wb], 1);
                        s_idx[wb][p] = n0 + i;
                        s_val[wb][p] = act[i];
                    }
                }

                op[(size_t)t * S4] = make_float4(act[0], act[1], act[2], act[3]);

                const float xs[VPT] = { xv.x, xv.y, xv.z, xv.w };
#pragma unroll
                for (int i = 0; i < VPT; i++) {
                    const float tot = xs[i] + rec[i];
                    const float st  = state[i] - act[i];
                    state[i] = st * ALPHA + OMA * tot;
                }

                __syncthreads();
                if (tid == 0) s_cnt[rb] = 0;
                __syncthreads();
                const int tmp = rb; rb = wb; wb = tmp;
            }
            pb = rb; qb = wb;   // last step's spikes ended up in rb; wb count is 0
        } else {
            const int tmp = pb; pb = qb; qb = tmp;   // qb list becomes prev list
        }
    }
}

extern "C" void kernel_launch(void* const* d_in, const int* in_sizes, int n_in,
                              void* d_out, int out_size)
{
    const float* x    = (const float*)d_in[0];   // input_current [B, T, N]
    const float* W    = (const float*)d_in[1];   // w_rec [N, N]
    const float* bias = (const float*)d_in[2];   // b_rec [N]
    float* out = (float*)d_out;

    const int N = in_sizes[2];                   // 1024
    const int T = 1000;
    const int B = in_sizes[0] / (T * N);         // 32

    lif_recurrent_kernel<<<B, THREADS>>>(x, W, bias, out, T);
}

// round 4
// speedup vs baseline: 2.4754x; 1.0420x over previous
#include <cuda_runtime.h>
#include <cuda_bf16.h>

// LIF recurrent scan, speculative-chunk version, v3.
//
// 1 CTA per batch row; membrane state in registers for all T steps; recurrent
// GEMM is a sparse rank-k update from a spike list (spikes ~6.5e-6 dense).
//
// v3: the speculative fast pass computes NO act for steps 0..CHUNK-2. A spike
// there (state >= 1.0) sets a shared flag via one predicated STS; the chunk is
// rolled back and replayed exactly (overwriting the zeros speculatively stored
// to `out`). Only the chunk's final step runs the full act/push path, since its
// spikes validly feed the next chunk. ~2x fewer common-path instructions; the
// kernel is issue-bound on its 32 active SMs.

#define N_NEU   1024
#define THREADS 256
#define VPT     4            // neurons per thread
#define CHUNK   8            // steps per speculation chunk (divides T=1000)

__device__ __forceinline__ float xv_comp(const float4& v, int i) {
    return (i == 0) ? v.x : (i == 1) ? v.y : (i == 2) ? v.z : v.w;
}

__global__ __launch_bounds__(THREADS, 1)
void lif_recurrent_kernel(const float* __restrict__ x,     // [B, T, N]
                          const float* __restrict__ W,     // [N, N] (out, in)
                          const float* __restrict__ bias,  // [N]
                          float* __restrict__ out,         // [B, T, N]
                          int T)
{
    const int b   = blockIdx.x;
    const int tid = threadIdx.x;
    const int n0  = tid * VPT;

    __shared__ int   s_idx[2][N_NEU];
    __shared__ float s_val[2][N_NEU];
    __shared__ int   s_cnt[2];
    __shared__ int   s_flag;
    if (tid < 2) s_cnt[tid] = 0;
    if (tid == 0) s_flag = 0;
    __syncthreads();

    float state[VPT], brec[VPT];
#pragma unroll
    for (int i = 0; i < VPT; i++) {
        state[i] = 0.0f;
        brec[i]  = bias[n0 + i];
    }

    const float4* xb = reinterpret_cast<const float4*>(
                           x + (size_t)b * T * N_NEU) + tid;
    float4* op = reinterpret_cast<float4*>(
                           out + (size_t)b * T * N_NEU) + tid;
    const int S4 = N_NEU / 4;

    // 2-deep input prefetch (replay reloads x directly; these regs untouched)
    float4 xv0 = xb[0];
    float4 xv1 = xb[S4];

    const float  ALPHA = 0.9f;
    const float  OMA   = 1.0f - 0.9f;

    int pb = 0, qb = 1;   // pb: prev-step spike list, qb: this chunk's output list

    for (int tc = 0; tc < T; tc += CHUNK) {
        const int c_prev = s_cnt[pb];

        float snap[VPT];
#pragma unroll
        for (int i = 0; i < VPT; i++) snap[i] = state[i];

        // ---------- fast speculative pass: no barriers, no act ----------
#pragma unroll
        for (int s = 0; s < CHUNK - 1; s++) {
            const int t = tc + s;
            float4 xv = xv0; xv0 = xv1;
            const int tp = min(t + 2, T - 1);          // IMNMX clamp
            xv1 = xb[(size_t)tp * S4];

            float rec[VPT];
#pragma unroll
            for (int i = 0; i < VPT; i++) rec[i] = brec[i];
            if (s == 0) {   // compile-time: only step 0 sees prev-chunk spikes
                for (int k = 0; k < c_prev; k++) {
                    const int   j = s_idx[pb][k];
                    const float v = s_val[pb][k];
#pragma unroll
                    for (int i = 0; i < VPT; i++)
                        rec[i] = fmaf(v, W[(size_t)(n0 + i) * N_NEU + j], rec[i]);
                }
            }

            // spike detector only: state >= 1.0  <=>  floor(state)>0 for state>0
            const float mx = fmaxf(fmaxf(state[0], state[1]),
                                   fmaxf(state[2], state[3]));
            if (mx >= 1.0f) s_flag = 1;        // single predicated STS (rare)

            // speculative output: zeros (replay overwrites on mis-speculation)
            op[(size_t)t * S4] = make_float4(0.f, 0.f, 0.f, 0.f);

            // membrane update with act = 0 (bit-identical to full expr at act=0)
#pragma unroll
            for (int i = 0; i < VPT; i++) {
                const float tot = xv_comp(xv, i) + rec[i];
                const float st  = state[i] - 0.0f;
                state[i] = st * ALPHA + OMA * tot;
            }
        }

        // ---------- last step of chunk: full exact path ----------
        {
            const int t = tc + CHUNK - 1;
            float4 xv = xv0; xv0 = xv1;
            const int tp = min(t + 2, T - 1);
            xv1 = xb[(size_t)tp * S4];

            float act[VPT];
#pragma unroll
            for (int i = 0; i < VPT; i++) {
                const float sv = state[i];
                act[i] = (sv > 0.0f) ? floorf(sv) : 0.0f;
            }
            const float sp = (act[0] + act[1]) + (act[2] + act[3]);
            if (sp != 0.0f) {                          // rare push
#pragma unroll
                for (int i = 0; i < VPT; i++)
                    if (act[i] != 0.0f) {
                        const int p = atomicAdd(&s_cnt[qb], 1);
                        s_idx[qb][p] = n0 + i;
                        s_val[qb][p] = act[i];
                    }
            }

            op[(size_t)t * S4] = make_float4(act[0], act[1], act[2], act[3]);

            const float xs[VPT] = { xv.x, xv.y, xv.z, xv.w };
#pragma unroll
            for (int i = 0; i < VPT; i++) {
                const float tot = xs[i] + brec[i];     // rec = bias for s > 0
                const float st  = state[i] - act[i];
                state[i] = st * ALPHA + OMA * tot;
            }
        }

        __syncthreads();                    // B1: flag & pushes visible
        const int f = s_flag;
        if (tid == 0 && !f) s_cnt[pb] = 0;  // retire prev list (commit only)
        __syncthreads();                    // B2: flag consumed by all

        if (f) {
            // ---------- rollback: exact replay with per-step barriers ----------
#pragma unroll
            for (int i = 0; i < VPT; i++) state[i] = snap[i];
            if (tid == 0) { s_cnt[qb] = 0; s_flag = 0; }
            __syncthreads();

            int rb = pb, wb = qb;
            for (int s = 0; s < CHUNK; s++) {
                const int t = tc + s;
                const int c = s_cnt[rb];
                const float4 xv = xb[(size_t)t * S4];

                float rec[VPT];
#pragma unroll
                for (int i = 0; i < VPT; i++) rec[i] = brec[i];
                for (int k = 0; k < c; k++) {
                    const int   j = s_idx[rb][k];
                    const float v = s_val[rb][k];
#pragma unroll
                    for (int i = 0; i < VPT; i++)
                        rec[i] = fmaf(v, W[(size_t)(n0 + i) * N_NEU + j], rec[i]);
                }

                float act[VPT];
#pragma unroll
                for (int i = 0; i < VPT; i++) {
                    const float sv = state[i];
                    act[i] = (sv > 0.0f) ? floorf(sv) : 0.0f;
                    if (act[i] != 0.0f) {
                        const int p = atomicAdd(&s_cnt[wb], 1);
                        s_idx[wb][p] = n0 + i;
                        s_val[wb][p] = act[i];
                    }
                }

                op[(size_t)t * S4] = make_float4(act[0], act[1], act[2], act[3]);

                const float xs[VPT] = { xv.x, xv.y, xv.z, xv.w };
#pragma unroll
                for (int i = 0; i < VPT; i++) {
                    const float tot = xs[i] + rec[i];
                    const float st  = state[i] - act[i];
                    state[i] = st * ALPHA + OMA * tot;
                }

                __syncthreads();
                if (tid == 0) s_cnt[rb] = 0;
                __syncthreads();
                const int tmp = rb; rb = wb; wb = tmp;
            }
            pb = rb; qb = wb;   // last step's spikes live in rb; wb count is 0
        } else {
            const int tmp = pb; pb = qb; qb = tmp;
        }
    }
}

extern "C" void kernel_launch(void* const* d_in, const int* in_sizes, int n_in,
                              void* d_out, int out_size)
{
    const float* x    = (const float*)d_in[0];   // input_current [B, T, N]
    const float* W    = (const float*)d_in[1];   // w_rec [N, N]
    const float* bias = (const float*)d_in[2];   // b_rec [N]
    float* out = (float*)d_out;

    const int N = in_sizes[2];                   // 1024
    const int T = 1000;
    const int B = in_sizes[0] / (T * N);         // 32

    lif_recurrent_kernel<<<B, THREADS>>>(x, W, bias, out, T);
}

// round 6
// speedup vs baseline: 2.9291x; 1.1833x over previous
#include <cuda_runtime.h>
#include <cuda_bf16.h>

// LIF recurrent scan, v4: speculative chunks + deep register prefetch.
//
// 1 CTA per batch row; membrane state in registers for all T steps; recurrent
// GEMM is a sparse rank-k update from a shared spike list (~6.5e-6 dense).
//
// v4 change (from ncu evidence): v3 was DRAM-latency-bound on the x stream
// (distance-2 prefetch, MLP=2, ~380cyc/step pacing). Now each chunk issues all
// CHUNK=10 of the NEXT chunk's LDG.128s up front into a register buffer
// (MLP=10, full-chunk latency cover). Fast pass does ZERO loads. Ping-pong
// buffers via double-instantiated chunk function (no copies). Replay (rare)
// reloads x from global so it needs no unrolling.

#define N_NEU   1024
#define THREADS 256
#define VPT     4            // neurons per thread
#define CHUNK   10           // steps per chunk; T=1000 = 50 * (2*CHUNK)

__device__ __forceinline__ void do_chunk(
    int tc, int T,
    float4 (&xcur)[CHUNK], float4 (&xnxt)[CHUNK],
    float (&state)[VPT], const float (&brec)[VPT],
    const float* __restrict__ W,
    const float4* __restrict__ xb,
    float4* __restrict__ op,
    int n0, int tid,
    int (&s_idx)[2][N_NEU], float (&s_val)[2][N_NEU],
    int (&s_cnt)[2], int& s_flag,
    int& pb, int& qb)
{
    const int   S4    = N_NEU / 4;
    const float ALPHA = 0.9f;
    const float OMA   = 1.0f - 0.9f;

    // ---- prefetch next chunk: CHUNK independent LDG.128s (MLP=CHUNK) ----
#pragma unroll
    for (int s = 0; s < CHUNK; s++) {
        const int tp = min(tc + CHUNK + s, T - 1);   // clamped; tail garbage unused
        xnxt[s] = xb[(size_t)tp * S4];
    }

    const int c_prev = s_cnt[pb];

    float snap[VPT];
#pragma unroll
    for (int i = 0; i < VPT; i++) snap[i] = state[i];

    // ---------- fast speculative pass: no loads, no barriers, no act ----------
#pragma unroll
    for (int s = 0; s < CHUNK - 1; s++) {
        const float4 xv = xcur[s];

        float rec[VPT];
#pragma unroll
        for (int i = 0; i < VPT; i++) rec[i] = brec[i];
        if (s == 0) {   // compile-time: only step 0 sees prev-chunk spikes
            for (int k = 0; k < c_prev; k++) {
                const int   j = s_idx[pb][k];
                const float v = s_val[pb][k];
#pragma unroll
                for (int i = 0; i < VPT; i++)
                    rec[i] = fmaf(v, W[(size_t)(n0 + i) * N_NEU + j], rec[i]);
            }
        }

        // spike detector only: any state >= 1.0 forces replay
        const float mx = fmaxf(fmaxf(state[0], state[1]),
                               fmaxf(state[2], state[3]));
        if (mx >= 1.0f) s_flag = 1;     // single predicated STS (rare)

        // speculative output: zeros (replay overwrites on mis-speculation)
        op[(size_t)(tc + s) * S4] = make_float4(0.f, 0.f, 0.f, 0.f);

        const float xs[VPT] = { xv.x, xv.y, xv.z, xv.w };
#pragma unroll
        for (int i = 0; i < VPT; i++) {
            const float tot = xs[i] + rec[i];
            const float st  = state[i] - 0.0f;      // act = 0 on fast path
            state[i] = st * ALPHA + OMA * tot;
        }
    }

    // ---------- last step of chunk: full exact path (spikes feed next) ----------
    {
        const float4 xv = xcur[CHUNK - 1];

        float act[VPT];
#pragma unroll
        for (int i = 0; i < VPT; i++) {
            const float sv = state[i];
            act[i] = (sv > 0.0f) ? floorf(sv) : 0.0f;
        }
        const float sp = (act[0] + act[1]) + (act[2] + act[3]);
        if (sp != 0.0f) {                           // rare push
#pragma unroll
            for (int i = 0; i < VPT; i++)
                if (act[i] != 0.0f) {
                    const int p = atomicAdd(&s_cnt[qb], 1);
                    s_idx[qb][p] = n0 + i;
                    s_val[qb][p] = act[i];
                }
        }

        op[(size_t)(tc + CHUNK - 1) * S4] =
            make_float4(act[0], act[1], act[2], act[3]);

        const float xs[VPT] = { xv.x, xv.y, xv.z, xv.w };
#pragma unroll
        for (int i = 0; i < VPT; i++) {
            const float tot = xs[i] + brec[i];      // rec = bias for s > 0
            const float st  = state[i] - act[i];
            state[i] = st * ALPHA + OMA * tot;
        }
    }

    __syncthreads();                    // B1: flag & pushes visible
    const int f = s_flag;
    if (tid == 0 && !f) s_cnt[pb] = 0;  // retire prev list (commit only)
    __syncthreads();                    // B2: flag consumed by all

    if (f) {
        // ---------- rollback: exact replay with per-step barriers ----------
#pragma unroll
        for (int i = 0; i < VPT; i++) state[i] = snap[i];
        if (tid == 0) { s_cnt[qb] = 0; s_flag = 0; }
        __syncthreads();

        int rb = pb, wb = qb;
#pragma unroll 1
        for (int s = 0; s < CHUNK; s++) {
            const int t = tc + s;
            const int c = s_cnt[rb];
            const float4 xv = xb[(size_t)t * S4];   // reload: same values as xcur[s]

            float rec[VPT];
#pragma unroll
            for (int i = 0; i < VPT; i++) rec[i] = brec[i];
            for (int k = 0; k < c; k++) {
                const int   j = s_idx[rb][k];
                const float v = s_val[rb][k];
#pragma unroll
                for (int i = 0; i < VPT; i++)
                    rec[i] = fmaf(v, W[(size_t)(n0 + i) * N_NEU + j], rec[i]);
            }

            float act[VPT];
#pragma unroll
            for (int i = 0; i < VPT; i++) {
                const float sv = state[i];
                act[i] = (sv > 0.0f) ? floorf(sv) : 0.0f;
                if (act[i] != 0.0f) {
                    const int p = atomicAdd(&s_cnt[wb], 1);
                    s_idx[wb][p] = n0 + i;
                    s_val[wb][p] = act[i];
                }
            }

            op[(size_t)t * S4] = make_float4(act[0], act[1], act[2], act[3]);

            const float xs[VPT] = { xv.x, xv.y, xv.z, xv.w };
#pragma unroll
            for (int i = 0; i < VPT; i++) {
                const float tot = xs[i] + rec[i];
                const float st  = state[i] - act[i];
                state[i] = st * ALPHA + OMA * tot;
            }

            __syncthreads();
            if (tid == 0) s_cnt[rb] = 0;
            __syncthreads();
            const int tmp = rb; rb = wb; wb = tmp;
        }
        pb = rb; qb = wb;   // last step's spikes live in rb; wb count is 0
    } else {
        const int tmp = pb; pb = qb; qb = tmp;
    }
}

__global__ __launch_bounds__(THREADS, 1)
void lif_recurrent_kernel(const float* __restrict__ x,     // [B, T, N]
                          const float* __restrict__ W,     // [N, N] (out, in)
                          const float* __restrict__ bias,  // [N]
                          float* __restrict__ out,         // [B, T, N]
                          int T)
{
    const int b   = blockIdx.x;
    const int tid = threadIdx.x;
    const int n0  = tid * VPT;

    __shared__ int   s_idx[2][N_NEU];
    __shared__ float s_val[2][N_NEU];
    __shared__ int   s_cnt[2];
    __shared__ int   s_flag;
    if (tid < 2) s_cnt[tid] = 0;
    if (tid == 0) s_flag = 0;
    __syncthreads();

    float state[VPT], brec[VPT];
#pragma unroll
    for (int i = 0; i < VPT; i++) {
        state[i] = 0.0f;
        brec[i]  = bias[n0 + i];
    }

    const float4* xb = reinterpret_cast<const float4*>(
                           x + (size_t)b * T * N_NEU) + tid;
    float4* op = reinterpret_cast<float4*>(
                           out + (size_t)b * T * N_NEU) + tid;
    const int S4 = N_NEU / 4;

    // preload chunk 0 into buffer A
    float4 xA[CHUNK], xB[CHUNK];
#pragma unroll
    for (int s = 0; s < CHUNK; s++) {
        const int tp = min(s, T - 1);
        xA[s] = xb[(size_t)tp * S4];
    }

    int pb = 0, qb = 1;

    // T must be a multiple of 2*CHUNK (1000 = 50 * 20)
    for (int tc = 0; tc < T; tc += 2 * CHUNK) {
        do_chunk(tc,         T, xA, xB, state, brec, W, xb, op, n0, tid,
                 s_idx, s_val, s_cnt, s_flag, pb, qb);
        do_chunk(tc + CHUNK, T, xB, xA, state, brec, W, xb, op, n0, tid,
                 s_idx, s_val, s_cnt, s_flag, pb, qb);
    }
}

extern "C" void kernel_launch(void* const* d_in, const int* in_sizes, int n_in,
                              void* d_out, int out_size)
{
    const float* x    = (const float*)d_in[0];   // input_current [B, T, N]
    const float* W    = (const float*)d_in[1];   // w_rec [N, N]
    const float* bias = (const float*)d_in[2];   // b_rec [N]
    float* out = (float*)d_out;

    const int N = in_sizes[2];                   // 1024
    const int T = 1000;
    const int B = in_sizes[0] / (T * N);         // 32

    lif_recurrent_kernel<<<B, THREADS>>>(x, W, bias, out, T);
}